// round 2
// baseline (speedup 1.0000x reference)
#include <cuda_runtime.h>
#include <cuda_bf16.h>
#include <cstdint>

// DRR renderer: line integrals of trilinearly-interpolated 256^3 volume along
// point-source -> detector rays.
//
// Strategy:
//  1) Transpose volume vol[i][j][k] -> g_volT[k][j][i] so that detector-x
//     (which maps to volume-x and varies fastest across a warp) is the
//     contiguous dimension. One-time 128MB traffic (~20us).
//  2) One thread per ray. Slab-clip the sample range to the volume AABB
//     (~35 of 128 samples survive). Per-sample trilinear with 8 coalesced
//     __ldg loads, 7-lerp reduction, fma-based.

#define DV 256
#define DV2 (DV * DV)

__device__ float g_volT[DV * DV * DV];  // 64 MB scratch, x-fastest layout

// -------- transpose: g_volT[k*DV2 + j*DV + i] = vol[i*DV2 + j*DV + k] --------
__global__ void transpose_vol(const float* __restrict__ v) {
    __shared__ float tile[32][33];
    const int j  = blockIdx.z;
    const int i0 = blockIdx.y * 32;
    const int k0 = blockIdx.x * 32;
    const int tx = threadIdx.x, ty = threadIdx.y;

#pragma unroll
    for (int n = 0; n < 4; n++) {
        int i = i0 + ty + n * 8;
        tile[ty + n * 8][tx] = v[(size_t)i * DV2 + j * DV + (k0 + tx)];
    }
    __syncthreads();
#pragma unroll
    for (int n = 0; n < 4; n++) {
        int k = k0 + ty + n * 8;
        g_volT[(size_t)k * DV2 + j * DV + (i0 + tx)] = tile[tx][ty + n * 8];
    }
}

// ----------------------------- main ray kernel ------------------------------
__global__ void __launch_bounds__(256) drr_kernel(
    const float* __restrict__ src,
    const float* __restrict__ tgt,
    const float* __restrict__ spacing,
    const float* __restrict__ origin,
    const int*   __restrict__ nptr,
    float* __restrict__ out,
    int n_rays)
{
    const int r = blockIdx.x * blockDim.x + threadIdx.x;
    if (r >= n_rays) return;

    const int n = nptr ? __ldg(nptr) : 128;

    const float ox = __ldg(origin + 0), oy = __ldg(origin + 1), oz = __ldg(origin + 2);
    const float hx = __ldg(spacing + 0), hy = __ldg(spacing + 1), hz = __ldg(spacing + 2);

    const float sxm = __ldg(src + 3 * r + 0);
    const float sym = __ldg(src + 3 * r + 1);
    const float szm = __ldg(src + 3 * r + 2);
    const float txm = __ldg(tgt + 3 * r + 0);
    const float tym = __ldg(tgt + 3 * r + 1);
    const float tzm = __ldg(tgt + 3 * r + 2);

    const float rx = txm - sxm, ry = tym - sym, rz = tzm - szm;
    const float raylen = sqrtf(fmaf(rx, rx, fmaf(ry, ry, rz * rz)));

    // voxel-space parametrization: idx(t) = p0 + t * d,  t = s/(n-1)
    const float p0x = (sxm - ox) / hx, p0y = (sym - oy) / hy, p0z = (szm - oz) / hz;
    const float dx = rx / hx, dy = ry / hy, dz = rz / hz;

    const float DM1 = (float)(DV - 1);

    // slab clip in t
    float tlo = 0.0f, thi = 1.0f;
    bool empty = false;
    {
        float p0[3] = {p0x, p0y, p0z};
        float dd[3] = {dx, dy, dz};
#pragma unroll
        for (int a = 0; a < 3; a++) {
            if (fabsf(dd[a]) > 1e-8f) {
                float inv = 1.0f / dd[a];
                float t1 = (0.0f - p0[a]) * inv;
                float t2 = (DM1 - p0[a]) * inv;
                tlo = fmaxf(tlo, fminf(t1, t2));
                thi = fminf(thi, fmaxf(t1, t2));
            } else if (p0[a] < 0.0f || p0[a] > DM1) {
                empty = true;
            }
        }
    }

    float acc = 0.0f;
    const float nm1 = (float)(n - 1);
    const float invn = (n > 1) ? 1.0f / nm1 : 0.0f;

    if (!empty && thi >= tlo) {
        int s0 = max(0, (int)floorf(tlo * nm1));
        int s1 = min(n - 1, (int)ceilf(thi * nm1));

#pragma unroll 4
        for (int s = s0; s <= s1; s++) {
            const float t  = (float)s * invn;
            const float ix = fmaf(t, dx, p0x);
            const float iy = fmaf(t, dy, p0y);
            const float iz = fmaf(t, dz, p0z);

            const bool inside = (ix >= 0.0f) & (ix <= DM1) &
                                (iy >= 0.0f) & (iy <= DM1) &
                                (iz >= 0.0f) & (iz <= DM1);
            if (inside) {
                const float fx = floorf(ix), fy = floorf(iy), fz = floorf(iz);
                const float wx = ix - fx, wy = iy - fy, wz = iz - fz;
                const int i0 = (int)fx, j0 = (int)fy, k0 = (int)fz;
                const int doffx = (i0 < DV - 1) ? 1 : 0;
                const int doffy = (j0 < DV - 1) ? DV : 0;
                const int doffz = (k0 < DV - 1) ? DV2 : 0;

                const float* b = g_volT + ((k0 * DV + j0) * DV + i0);

                const float v000 = __ldg(b);
                const float v100 = __ldg(b + doffx);
                const float v010 = __ldg(b + doffy);
                const float v110 = __ldg(b + doffy + doffx);
                const float v001 = __ldg(b + doffz);
                const float v101 = __ldg(b + doffz + doffx);
                const float v011 = __ldg(b + doffz + doffy);
                const float v111 = __ldg(b + doffz + doffy + doffx);

                // 7-lerp trilinear: lerp(a,b,w) = fma(w, b-a, a)
                const float c00 = fmaf(wx, v100 - v000, v000);
                const float c01 = fmaf(wx, v110 - v010, v010);
                const float c10 = fmaf(wx, v101 - v001, v001);
                const float c11 = fmaf(wx, v111 - v011, v011);
                const float c0  = fmaf(wy, c01 - c00, c00);
                const float c1  = fmaf(wy, c11 - c10, c10);
                acc += fmaf(wz, c1 - c0, c0);
            }
        }
    }

    out[r] = acc * raylen / (float)n;
}

extern "C" void kernel_launch(void* const* d_in, const int* in_sizes, int n_in,
                              void* d_out, int out_size) {
    const float* src     = (const float*)d_in[0];
    const float* tgt     = (const float*)d_in[1];
    const float* density = (const float*)d_in[2];
    const float* spacing = (const float*)d_in[3];
    const float* origin  = (const float*)d_in[4];
    const int*   nptr    = (n_in > 5) ? (const int*)d_in[5] : nullptr;
    float* out = (float*)d_out;

    // 1) transpose volume into x-fastest scratch
    dim3 tb(32, 8);
    dim3 tg(DV / 32, DV / 32, DV);
    transpose_vol<<<tg, tb>>>(density);

    // 2) one thread per ray
    const int threads = 256;
    const int blocks  = (out_size + threads - 1) / threads;
    drr_kernel<<<blocks, threads>>>(src, tgt, spacing, origin, nptr, out, out_size);
}

// round 3
// speedup vs baseline: 1.3279x; 1.3279x over previous
#include <cuda_runtime.h>
#include <cuda_fp16.h>
#include <cstdint>

// DRR renderer: line integrals of trilinearly-interpolated 256^3 volume along
// point-source -> detector rays.
//
// R2 strategy:
//  1) Transpose volume vol[i][j][k] -> g_volT[k][j][i] (x fastest) AND store
//     as fp16: halves transpose store traffic and makes the volume (32 MB)
//     fully L2-resident for the ray kernel.
//  2) TWO threads per ray (even/odd samples) + shfl reduce: doubles thread
//     count -> occupancy 38% -> ~75%, hiding load latency.

#define DV 256
#define DV2 (DV * DV)

__device__ __half g_volT[DV * DV * DV];  // 32 MB, x-fastest layout

// -------- transpose: g_volT[k*DV2 + j*DV + i] = (half)vol[i*DV2 + j*DV + k] --------
// tile: 64 i-values x 32 k-values per block, one j slice.
__global__ void __launch_bounds__(256) transpose_vol(const float* __restrict__ v) {
    __shared__ float tile[32][65];            // [k_local][i_local(64)+pad]
    const int j  = blockIdx.z;
    const int i0 = blockIdx.y * 64;
    const int k0 = blockIdx.x * 32;
    const int tx = threadIdx.x, ty = threadIdx.y;

#pragma unroll
    for (int n = 0; n < 8; n++) {
        const int il = ty + n * 8;
        tile[tx][il] = v[(size_t)(i0 + il) * DV2 + j * DV + (k0 + tx)];
    }
    __syncthreads();
#pragma unroll
    for (int n = 0; n < 4; n++) {
        const int kl = ty + n * 8;
        const __half2 h = __floats2half2_rn(tile[kl][2 * tx], tile[kl][2 * tx + 1]);
        ((__half2*)g_volT)[(((size_t)(k0 + kl) * DV2 + j * DV + i0) >> 1) + tx] = h;
    }
}

// ----------------------------- main ray kernel ------------------------------
// 2 threads per ray: sub-thread handles samples s0+sub, s0+sub+2, ...
__global__ void __launch_bounds__(256) drr_kernel(
    const float* __restrict__ src,
    const float* __restrict__ tgt,
    const float* __restrict__ spacing,
    const float* __restrict__ origin,
    const int*   __restrict__ nptr,
    float* __restrict__ out,
    int n_rays)
{
    const int tid = blockIdx.x * blockDim.x + threadIdx.x;
    const int r   = tid >> 1;
    const int sub = tid & 1;
    if (r >= n_rays) return;

    const int n = nptr ? __ldg(nptr) : 128;

    const float ox = __ldg(origin + 0), oy = __ldg(origin + 1), oz = __ldg(origin + 2);
    const float hx = __ldg(spacing + 0), hy = __ldg(spacing + 1), hz = __ldg(spacing + 2);

    const float sxm = __ldg(src + 3 * r + 0);
    const float sym = __ldg(src + 3 * r + 1);
    const float szm = __ldg(src + 3 * r + 2);
    const float txm = __ldg(tgt + 3 * r + 0);
    const float tym = __ldg(tgt + 3 * r + 1);
    const float tzm = __ldg(tgt + 3 * r + 2);

    const float rx = txm - sxm, ry = tym - sym, rz = tzm - szm;
    const float raylen = sqrtf(fmaf(rx, rx, fmaf(ry, ry, rz * rz)));

    // voxel-space parametrization: idx(t) = p0 + t * d,  t = s/(n-1)
    const float p0x = (sxm - ox) / hx, p0y = (sym - oy) / hy, p0z = (szm - oz) / hz;
    const float dx = rx / hx, dy = ry / hy, dz = rz / hz;

    const float DM1 = (float)(DV - 1);

    // slab clip in t
    float tlo = 0.0f, thi = 1.0f;
    bool empty = false;
    {
        float p0[3] = {p0x, p0y, p0z};
        float dd[3] = {dx, dy, dz};
#pragma unroll
        for (int a = 0; a < 3; a++) {
            if (fabsf(dd[a]) > 1e-8f) {
                float inv = 1.0f / dd[a];
                float t1 = (0.0f - p0[a]) * inv;
                float t2 = (DM1 - p0[a]) * inv;
                tlo = fmaxf(tlo, fminf(t1, t2));
                thi = fminf(thi, fmaxf(t1, t2));
            } else if (p0[a] < 0.0f || p0[a] > DM1) {
                empty = true;
            }
        }
    }

    float acc = 0.0f;
    const float nm1 = (float)(n - 1);
    const float invn = (n > 1) ? 1.0f / nm1 : 0.0f;

    if (!empty && thi >= tlo) {
        const int s0 = max(0, (int)floorf(tlo * nm1));
        const int s1 = min(n - 1, (int)ceilf(thi * nm1));

#pragma unroll 4
        for (int s = s0 + sub; s <= s1; s += 2) {
            const float t  = (float)s * invn;
            const float ix = fmaf(t, dx, p0x);
            const float iy = fmaf(t, dy, p0y);
            const float iz = fmaf(t, dz, p0z);

            const bool inside = (ix >= 0.0f) & (ix <= DM1) &
                                (iy >= 0.0f) & (iy <= DM1) &
                                (iz >= 0.0f) & (iz <= DM1);
            if (inside) {
                const float fx = floorf(ix), fy = floorf(iy), fz = floorf(iz);
                const float wx = ix - fx, wy = iy - fy, wz = iz - fz;
                const int i0 = (int)fx, j0 = (int)fy, k0 = (int)fz;
                const int doffx = (i0 < DV - 1) ? 1 : 0;
                const int doffy = (j0 < DV - 1) ? DV : 0;
                const int doffz = (k0 < DV - 1) ? DV2 : 0;

                const __half* b = g_volT + ((k0 * DV + j0) * DV + i0);

                const float v000 = __half2float(__ldg(b));
                const float v100 = __half2float(__ldg(b + doffx));
                const float v010 = __half2float(__ldg(b + doffy));
                const float v110 = __half2float(__ldg(b + doffy + doffx));
                const float v001 = __half2float(__ldg(b + doffz));
                const float v101 = __half2float(__ldg(b + doffz + doffx));
                const float v011 = __half2float(__ldg(b + doffz + doffy));
                const float v111 = __half2float(__ldg(b + doffz + doffy + doffx));

                // 7-lerp trilinear: lerp(a,b,w) = fma(w, b-a, a)
                const float c00 = fmaf(wx, v100 - v000, v000);
                const float c01 = fmaf(wx, v110 - v010, v010);
                const float c10 = fmaf(wx, v101 - v001, v001);
                const float c11 = fmaf(wx, v111 - v011, v011);
                const float c0  = fmaf(wy, c01 - c00, c00);
                const float c1  = fmaf(wy, c11 - c10, c10);
                acc += fmaf(wz, c1 - c0, c0);
            }
        }
    }

    // pair reduction across the 2 sub-threads of this ray
    acc += __shfl_xor_sync(0xFFFFFFFFu, acc, 1);

    if (sub == 0) out[r] = acc * raylen / (float)n;
}

extern "C" void kernel_launch(void* const* d_in, const int* in_sizes, int n_in,
                              void* d_out, int out_size) {
    const float* src     = (const float*)d_in[0];
    const float* tgt     = (const float*)d_in[1];
    const float* density = (const float*)d_in[2];
    const float* spacing = (const float*)d_in[3];
    const float* origin  = (const float*)d_in[4];
    const int*   nptr    = (n_in > 5) ? (const int*)d_in[5] : nullptr;
    float* out = (float*)d_out;

    // 1) transpose volume into x-fastest fp16 scratch
    dim3 tb(32, 8);
    dim3 tg(DV / 32, DV / 64, DV);
    transpose_vol<<<tg, tb>>>(density);

    // 2) two threads per ray
    const int threads = 256;
    const int total   = out_size * 2;
    const int blocks  = (total + threads - 1) / threads;
    drr_kernel<<<blocks, threads>>>(src, tgt, spacing, origin, nptr, out, out_size);
}